// round 3
// baseline (speedup 1.0000x reference)
#include <cuda_runtime.h>
#include <cstdint>

#define N_NODES 59392
#define F_IN    116
#define H_DIM   256
#define N_EDGES 950272
#define E_DIM   5
#define EMB     16
#define K_IN    (F_IN + EMB)   // 132
#define BN_EPS  1e-5f

// ---------------- scratch (no allocations allowed) ----------------
__device__ float g_h  [(size_t)N_NODES * H_DIM];
__device__ float g_agg[(size_t)N_NODES * H_DIM];
__device__ float g_tmp[(size_t)N_NODES * H_DIM];
__device__ float g_sum[H_DIM];
__device__ float g_sumsq[H_DIM];
__device__ float g_scale[H_DIM];
__device__ float g_shift[H_DIM];
__device__ int   g_src[N_EDGES];
__device__ int   g_dst[N_EDGES];
__device__ int   g_gid[N_NODES];
__device__ int   g_is64;

// ---------------- dtype probe: int64 vs int32 index buffers ----------------
// int64 indices < 2^31 little-endian => every odd 32-bit word is 0.
// int32 indices in [0, 59392) random => 128 consecutive odd words all-zero is impossible.
__global__ void detect_kernel(const int* __restrict__ ei_words) {
    if (threadIdx.x == 0) {
        int all_zero = 1;
        for (int i = 1; i < 256; i += 2)
            if (ei_words[i] != 0) { all_zero = 0; break; }
        g_is64 = all_zero;
    }
}

// normalize edge_index and group_ids into int32 scratch (works for both dtypes)
__global__ __launch_bounds__(256)
void convert_kernel(const void* __restrict__ ei, const void* __restrict__ gid) {
    const int is64 = g_is64;
    const long long* ei64  = (const long long*)ei;
    const int*       ei32  = (const int*)ei;
    const long long* gid64 = (const long long*)gid;
    const int*       gid32 = (const int*)gid;
    size_t stride = (size_t)gridDim.x * blockDim.x;
    for (size_t e = (size_t)blockIdx.x * blockDim.x + threadIdx.x; e < N_EDGES; e += stride) {
        if (is64) {
            g_src[e] = (int)ei64[e];
            g_dst[e] = (int)ei64[(size_t)N_EDGES + e];
        } else {
            g_src[e] = ei32[e];
            g_dst[e] = ei32[(size_t)N_EDGES + e];
        }
    }
    for (size_t n = (size_t)blockIdx.x * blockDim.x + threadIdx.x; n < N_NODES; n += stride)
        g_gid[n] = is64 ? (int)gid64[n] : gid32[n];
}

// ---------------- zero agg + stats ----------------
__global__ void zero_kernel() {
    size_t total = (size_t)N_NODES * H_DIM;
    size_t stride = (size_t)gridDim.x * blockDim.x;
    for (size_t i = (size_t)blockIdx.x * blockDim.x + threadIdx.x; i < total; i += stride)
        g_agg[i] = 0.0f;
    if (blockIdx.x == 0 && threadIdx.x < H_DIM) {
        g_sum[threadIdx.x]   = 0.0f;
        g_sumsq[threadIdx.x] = 0.0f;
    }
}

// ---------------- tiled fp32 GEMM ----------------
// dst[M x 256] = relu(A[M x K] @ W[K x 256] + bias)
// MODE 0: A = concat(x, group_emb[g_gid])  (K = 132), dst = g_h
// MODE 1: A = g_h + g_agg                  (K = 256), dst = g_tmp
// MODE 2: A = g_tmp                        (K = 256), dst = out param
// BM=128, BN=64, BK=16, 256 threads, 8x4 micro-tile per thread.
template <int MODE>
__global__ __launch_bounds__(256)
void gemm_kernel(const float* __restrict__ X,
                 const float* __restrict__ Gemb,
                 const float* __restrict__ W,
                 const float* __restrict__ bias,
                 float* __restrict__ out_param,
                 int K)
{
    const int BM = 128, BN = 64, BK = 16;
    __shared__ float As[BK][BM + 4];
    __shared__ float Bs[BK][BN];
    __shared__ int   sgid[BM];

    const int row0 = blockIdx.x * BM;
    const int col0 = blockIdx.y * BN;
    const int tid  = threadIdx.x;
    const int tx   = tid & 15;   // 16 col-groups of 4 cols
    const int ty   = tid >> 4;   // 16 row-groups of 8 rows

    if (MODE == 0) {
        if (tid < BM) sgid[tid] = g_gid[row0 + tid];
        __syncthreads();
    }

    float acc[8][4];
#pragma unroll
    for (int r = 0; r < 8; r++)
#pragma unroll
        for (int c = 0; c < 4; c++) acc[r][c] = 0.0f;

    for (int k0 = 0; k0 < K; k0 += BK) {
        // load A tile (transposed into As[k][m])
#pragma unroll
        for (int i = 0; i < 8; i++) {
            int idx = tid + i * 256;
            int m   = idx >> 4;
            int kk  = idx & 15;
            int k   = k0 + kk;
            float v = 0.0f;
            if (k < K) {
                int row = row0 + m;
                if (MODE == 0) {
                    v = (k < F_IN) ? X[(size_t)row * F_IN + k]
                                   : Gemb[sgid[m] * EMB + (k - F_IN)];
                } else if (MODE == 1) {
                    size_t o = (size_t)row * H_DIM + k;
                    v = g_h[o] + g_agg[o];
                } else {
                    v = g_tmp[(size_t)row * H_DIM + k];
                }
            }
            As[kk][m] = v;
        }
        // load B tile
#pragma unroll
        for (int i = 0; i < 4; i++) {
            int idx = tid + i * 256;
            int kk  = idx >> 6;
            int n   = idx & 63;
            int k   = k0 + kk;
            Bs[kk][n] = (k < K) ? W[(size_t)k * H_DIM + col0 + n] : 0.0f;
        }
        __syncthreads();

#pragma unroll
        for (int kk = 0; kk < BK; kk++) {
            float a[8], b[4];
#pragma unroll
            for (int r = 0; r < 8; r++) a[r] = As[kk][ty * 8 + r];
#pragma unroll
            for (int c = 0; c < 4; c++) b[c] = Bs[kk][tx * 4 + c];
#pragma unroll
            for (int r = 0; r < 8; r++)
#pragma unroll
                for (int c = 0; c < 4; c++)
                    acc[r][c] = fmaf(a[r], b[c], acc[r][c]);
        }
        __syncthreads();
    }

    // epilogue: bias + relu -> destination selected at compile time
    float* dst = (MODE == 0) ? g_h : (MODE == 1) ? g_tmp : out_param;
#pragma unroll
    for (int r = 0; r < 8; r++) {
        int row = row0 + ty * 8 + r;
#pragma unroll
        for (int c = 0; c < 4; c++) {
            int col = col0 + tx * 4 + c;
            float v = acc[r][c] + bias[col];
            dst[(size_t)row * H_DIM + col] = fmaxf(v, 0.0f);
        }
    }
}

// ---------------- BatchNorm ----------------
__global__ __launch_bounds__(256)
void bn_stats_kernel() {
    int c = threadIdx.x;   // 256 channels
    float s = 0.0f, s2 = 0.0f;
    for (int r = blockIdx.x; r < N_NODES; r += gridDim.x) {
        float v = g_h[(size_t)r * H_DIM + c];
        s += v;
        s2 += v * v;
    }
    atomicAdd(&g_sum[c], s);
    atomicAdd(&g_sumsq[c], s2);
}

__global__ void bn_finalize_kernel(const float* __restrict__ gamma,
                                   const float* __restrict__ beta) {
    int c = threadIdx.x;
    float invN = 1.0f / (float)N_NODES;
    float mu   = g_sum[c] * invN;
    float var  = fmaxf(g_sumsq[c] * invN - mu * mu, 0.0f);
    float rs   = rsqrtf(var + BN_EPS);
    float sc   = rs * gamma[c];
    g_scale[c] = sc;
    g_shift[c] = beta[c] - mu * sc;
}

__global__ __launch_bounds__(256)
void bn_apply_kernel() {
    size_t total4 = (size_t)N_NODES * H_DIM / 4;
    size_t stride = (size_t)gridDim.x * blockDim.x;
    float4* h4 = reinterpret_cast<float4*>(g_h);
    for (size_t i = (size_t)blockIdx.x * blockDim.x + threadIdx.x; i < total4; i += stride) {
        int c0 = (int)((i * 4) & (H_DIM - 1));
        float4 v = h4[i];
        v.x = v.x * g_scale[c0 + 0] + g_shift[c0 + 0];
        v.y = v.y * g_scale[c0 + 1] + g_shift[c0 + 1];
        v.z = v.z * g_scale[c0 + 2] + g_shift[c0 + 2];
        v.w = v.w * g_scale[c0 + 3] + g_shift[c0 + 3];
        h4[i] = v;
    }
}

// ---------------- GINE edge kernel ----------------
// warp per edge (grid-stride). lane owns cols [8*lane, 8*lane+8).
// msg = relu(h[src] + edge_attr @ We + be); agg[dst] += msg (vector red).
__global__ __launch_bounds__(256)
void edge_kernel(const float* __restrict__ ea,
                 const float* __restrict__ We,
                 const float* __restrict__ be)
{
    const int lane   = threadIdx.x & 31;
    const int warp   = (blockIdx.x * blockDim.x + threadIdx.x) >> 5;
    const int nwarps = (gridDim.x * blockDim.x) >> 5;
    const int cbase  = lane * 8;

    float we[E_DIM][8], bvec[8];
#pragma unroll
    for (int d = 0; d < E_DIM; d++)
#pragma unroll
        for (int j = 0; j < 8; j++)
            we[d][j] = We[d * H_DIM + cbase + j];
#pragma unroll
    for (int j = 0; j < 8; j++) bvec[j] = be[cbase + j];

    for (int e = warp; e < N_EDGES; e += nwarps) {
        int src = g_src[e];
        int dst = g_dst[e];
        float eav = (lane < E_DIM) ? ea[(size_t)e * E_DIM + lane] : 0.0f;

        float acc[8];
#pragma unroll
        for (int j = 0; j < 8; j++) acc[j] = bvec[j];
#pragma unroll
        for (int d = 0; d < E_DIM; d++) {
            float v = __shfl_sync(0xffffffffu, eav, d);
#pragma unroll
            for (int j = 0; j < 8; j++) acc[j] = fmaf(v, we[d][j], acc[j]);
        }

        const float4* hp = reinterpret_cast<const float4*>(&g_h[(size_t)src * H_DIM + cbase]);
        float4 h0 = hp[0];
        float4 h1 = hp[1];

        float m0 = fmaxf(h0.x + acc[0], 0.0f);
        float m1 = fmaxf(h0.y + acc[1], 0.0f);
        float m2 = fmaxf(h0.z + acc[2], 0.0f);
        float m3 = fmaxf(h0.w + acc[3], 0.0f);
        float m4 = fmaxf(h1.x + acc[4], 0.0f);
        float m5 = fmaxf(h1.y + acc[5], 0.0f);
        float m6 = fmaxf(h1.z + acc[6], 0.0f);
        float m7 = fmaxf(h1.w + acc[7], 0.0f);

        float* ap = &g_agg[(size_t)dst * H_DIM + cbase];
        unsigned long long gaddr = (unsigned long long)__cvta_generic_to_global((void*)ap);
        asm volatile("red.global.add.v4.f32 [%0], {%1,%2,%3,%4};"
                     :: "l"(gaddr), "f"(m0), "f"(m1), "f"(m2), "f"(m3) : "memory");
        asm volatile("red.global.add.v4.f32 [%0], {%1,%2,%3,%4};"
                     :: "l"(gaddr + 16), "f"(m4), "f"(m5), "f"(m6), "f"(m7) : "memory");
    }
}

// ---------------- edge_attr passthrough (2nd tuple element) ----------------
__global__ __launch_bounds__(256)
void copy_kernel(const float* __restrict__ src, float* __restrict__ dst, size_t n4) {
    size_t stride = (size_t)gridDim.x * blockDim.x;
    const float4* s4 = reinterpret_cast<const float4*>(src);
    float4* d4 = reinterpret_cast<float4*>(dst);
    for (size_t i = (size_t)blockIdx.x * blockDim.x + threadIdx.x; i < n4; i += stride)
        d4[i] = s4[i];
}

// ---------------- launch ----------------
extern "C" void kernel_launch(void* const* d_in, const int* in_sizes, int n_in,
                              void* d_out, int out_size)
{
    // ---- input order detection by size signature ----
    // dict (insertion) order signature:
    static const long long SZ_DICT[15] = {
        6889472LL, 1900544LL, 4751360LL, 59392LL, 128LL, 33792LL, 256LL,
        256LL, 256LL, 1280LL, 256LL, 65536LL, 256LL, 65536LL, 256LL };
    // alphabetical order (W1,W2,W_in,We,b1,b2,b_in,be,beta,edge_attr,
    //                     edge_index,gamma,group_emb,group_ids,x) signature:
    static const long long SZ_ALPHA[15] = {
        65536LL, 65536LL, 33792LL, 1280LL, 256LL, 256LL, 256LL, 256LL,
        256LL, 4751360LL, 1900544LL, 256LL, 128LL, 59392LL, 6889472LL };
    // alpha position -> dict role
    static const int ALPHA_TO_DICT[15] = { 11, 13, 5, 9, 12, 14, 6, 10, 8, 2, 1, 7, 4, 3, 0 };

    int perm[15];                       // perm[dict_role] = d_in index
    for (int i = 0; i < 15; i++) perm[i] = i;   // default: dict order
    if (n_in >= 15) {
        bool dict_ok = true, alpha_ok = true;
        for (int i = 0; i < 15; i++) {
            if ((long long)in_sizes[i] != SZ_DICT[i])  dict_ok  = false;
            if ((long long)in_sizes[i] != SZ_ALPHA[i]) alpha_ok = false;
        }
        if (!dict_ok && alpha_ok)
            for (int i = 0; i < 15; i++) perm[ALPHA_TO_DICT[i]] = i;
    }

    const float* x      = (const float*)d_in[perm[0]];
    const void*  eindex = d_in[perm[1]];
    const float* eattr  = (const float*)d_in[perm[2]];
    const void*  gids   = d_in[perm[3]];
    const float* gemb   = (const float*)d_in[perm[4]];
    const float* W_in   = (const float*)d_in[perm[5]];
    const float* b_in   = (const float*)d_in[perm[6]];
    const float* gamma  = (const float*)d_in[perm[7]];
    const float* beta   = (const float*)d_in[perm[8]];
    const float* We     = (const float*)d_in[perm[9]];
    const float* be     = (const float*)d_in[perm[10]];
    const float* W1     = (const float*)d_in[perm[11]];
    const float* b1     = (const float*)d_in[perm[12]];
    const float* W2     = (const float*)d_in[perm[13]];
    const float* b2     = (const float*)d_in[perm[14]];
    float* out = (float*)d_out;

    dim3 ggrid(N_NODES / 128, H_DIM / 64);

    // 0. dtype probe + index normalization (int64 vs int32)
    detect_kernel<<<1, 32>>>((const int*)eindex);
    convert_kernel<<<2048, 256>>>(eindex, gids);

    // 1. zero agg + stats
    zero_kernel<<<2048, 256>>>();

    // 2. h = relu(concat(x, emb) @ W_in + b_in)   -> g_h
    gemm_kernel<0><<<ggrid, 256>>>(x, gemb, W_in, b_in, nullptr, K_IN);

    // 3-5. BatchNorm (training stats, biased var), applied in-place on g_h
    bn_stats_kernel<<<464, 256>>>();
    bn_finalize_kernel<<<1, 256>>>(gamma, beta);
    bn_apply_kernel<<<1024, 256>>>();

    // 6. GINE edge scatter: agg[dst] += relu(h[src] + ea@We + be)
    edge_kernel<<<4096, 256>>>(eattr, We, be);

    // 7. tmp = relu((h + agg) @ W1 + b1)   -> g_tmp
    gemm_kernel<1><<<ggrid, 256>>>(nullptr, nullptr, W1, b1, nullptr, H_DIM);

    // 8. out = relu(tmp @ W2 + b2)         -> d_out
    gemm_kernel<2><<<ggrid, 256>>>(nullptr, nullptr, W2, b2, out, H_DIM);

    // 9. second tuple element: edge_attr passthrough (size derived from out_size)
    long long tail = (long long)out_size - (long long)N_NODES * H_DIM;
    if (tail > 0) {
        size_t n4 = (size_t)tail / 4;   // E*ED = 4,751,360 floats, divisible by 4
        copy_kernel<<<2048, 256>>>(eattr, out + (size_t)N_NODES * H_DIM, n4);
    }
}

// round 4
// speedup vs baseline: 1.3324x; 1.3324x over previous
#include <cuda_runtime.h>
#include <cstdint>

#define N_NODES 59392
#define F_IN    116
#define H_DIM   256
#define N_EDGES 950272
#define E_DIM   5
#define EMB     16
#define K_IN    (F_IN + EMB)   // 132
#define BN_EPS  1e-5f

// ---------------- scratch (no allocations allowed) ----------------
__device__ float g_h  [(size_t)N_NODES * H_DIM];
__device__ float g_agg[(size_t)N_NODES * H_DIM];
__device__ float g_tmp[(size_t)N_NODES * H_DIM];
__device__ float g_sum[H_DIM];
__device__ float g_sumsq[H_DIM];
__device__ float g_scale[H_DIM];
__device__ float g_shift[H_DIM];
__device__ int   g_src[N_EDGES];
__device__ int   g_dst[N_EDGES];
__device__ int   g_gid[N_NODES];
__device__ int   g_is64;

// ---------------- dtype probe: int64 vs int32 index buffers ----------------
__global__ void detect_kernel(const int* __restrict__ ei_words) {
    if (threadIdx.x == 0) {
        int all_zero = 1;
        for (int i = 1; i < 256; i += 2)
            if (ei_words[i] != 0) { all_zero = 0; break; }
        g_is64 = all_zero;
    }
}

// normalize edge_index and group_ids into int32 scratch (works for both dtypes)
__global__ __launch_bounds__(256)
void convert_kernel(const void* __restrict__ ei, const void* __restrict__ gid) {
    const int is64 = g_is64;
    const long long* ei64  = (const long long*)ei;
    const int*       ei32  = (const int*)ei;
    const long long* gid64 = (const long long*)gid;
    const int*       gid32 = (const int*)gid;
    size_t stride = (size_t)gridDim.x * blockDim.x;
    for (size_t e = (size_t)blockIdx.x * blockDim.x + threadIdx.x; e < N_EDGES; e += stride) {
        if (is64) {
            g_src[e] = (int)ei64[e];
            g_dst[e] = (int)ei64[(size_t)N_EDGES + e];
        } else {
            g_src[e] = ei32[e];
            g_dst[e] = ei32[(size_t)N_EDGES + e];
        }
    }
    for (size_t n = (size_t)blockIdx.x * blockDim.x + threadIdx.x; n < N_NODES; n += stride)
        g_gid[n] = is64 ? (int)gid64[n] : gid32[n];
}

// ---------------- zero agg + stats ----------------
__global__ __launch_bounds__(256)
void zero_kernel() {
    size_t total4 = (size_t)N_NODES * H_DIM / 4;
    size_t stride = (size_t)gridDim.x * blockDim.x;
    float4* a4 = reinterpret_cast<float4*>(g_agg);
    float4 z = make_float4(0.f, 0.f, 0.f, 0.f);
    for (size_t i = (size_t)blockIdx.x * blockDim.x + threadIdx.x; i < total4; i += stride)
        a4[i] = z;
    if (blockIdx.x == 0 && threadIdx.x < H_DIM) {
        g_sum[threadIdx.x]   = 0.0f;
        g_sumsq[threadIdx.x] = 0.0f;
    }
}

// ---------------- f32x2 packed-FMA tiled GEMM ----------------
// dst[M x 256] = relu(A[M x K] @ W[K x 256] + bias)
// MODE 0: A = concat(x, group_emb[g_gid])  (K = 132), dst = g_h
// MODE 1: A = g_h + g_agg                  (K = 256), dst = g_tmp
// MODE 2: A = g_tmp                        (K = 256), dst = out param
// BM=128, BN=128, BK=16, 256 threads, 8x8 micro-tile via 4x8 f32x2 pairs.
template <int MODE>
__global__ __launch_bounds__(256, 2)
void gemm_kernel(const float* __restrict__ X,
                 const float* __restrict__ Gemb,
                 const float* __restrict__ W,
                 const float* __restrict__ bias,
                 float* __restrict__ out_param,
                 int K)
{
    const int BM = 128, BN = 128, BK = 16;
    __shared__ __align__(16) float As[BK][BM + 2];   // k-major, pad 2 (conflict-free)
    __shared__ __align__(16) float Bs[BK][BN];
    __shared__ int sgid[BM];

    const int row0 = blockIdx.x * BM;
    const int col0 = blockIdx.y * BN;
    const int tid  = threadIdx.x;
    const int tx   = tid & 15;    // column group
    const int ty   = tid >> 4;    // row group (8 rows)

    if (MODE == 0) {
        if (tid < BM) sgid[tid] = g_gid[row0 + tid];
        __syncthreads();
    }

    // acc[rp][c]: packed pair = (row 2rp, row 2rp+1) within ty's 8 rows.
    // c<4 -> col = col0 + tx*4 + c ; c>=4 -> col = col0 + 64 + tx*4 + (c-4)
    unsigned long long acc[4][8];
#pragma unroll
    for (int rp = 0; rp < 4; rp++)
#pragma unroll
        for (int c = 0; c < 8; c++) acc[rp][c] = 0ULL;

    const int ntiles = (K + BK - 1) / BK;
    for (int kt = 0; kt < ntiles; kt++) {
        const int k0 = kt * BK;

        // ---- stage A tile (transposed to As[k][m]) : 2 x float4 per thread ----
#pragma unroll
        for (int i = 0; i < 2; i++) {
            int idx = tid + i * 256;          // 0..511
            int m   = idx >> 2;               // 0..127
            int kq  = idx & 3;                // float4 index within BK
            int k   = k0 + kq * 4;
            int row = row0 + m;
            float4 v;
            if (MODE == 0) {
                float vv[4];
#pragma unroll
                for (int j = 0; j < 4; j++) {
                    int kj = k + j;
                    vv[j] = (kj < K) ? ((kj < F_IN) ? X[(size_t)row * F_IN + kj]
                                                    : Gemb[sgid[m] * EMB + (kj - F_IN)])
                                     : 0.0f;
                }
                v = make_float4(vv[0], vv[1], vv[2], vv[3]);
            } else if (MODE == 1) {
                float4 a = *reinterpret_cast<const float4*>(&g_h  [(size_t)row * H_DIM + k]);
                float4 b = *reinterpret_cast<const float4*>(&g_agg[(size_t)row * H_DIM + k]);
                v = make_float4(a.x + b.x, a.y + b.y, a.z + b.z, a.w + b.w);
            } else {
                v = *reinterpret_cast<const float4*>(&g_tmp[(size_t)row * H_DIM + k]);
            }
            As[kq * 4 + 0][m] = v.x;
            As[kq * 4 + 1][m] = v.y;
            As[kq * 4 + 2][m] = v.z;
            As[kq * 4 + 3][m] = v.w;
        }
        // ---- stage B tile : 2 x float4 per thread ----
#pragma unroll
        for (int i = 0; i < 2; i++) {
            int idx = tid + i * 256;          // 0..511
            int kk  = idx >> 5;               // 0..15
            int n   = (idx & 31) * 4;         // 0..124
            int k   = k0 + kk;
            float4 v = make_float4(0.f, 0.f, 0.f, 0.f);
            if (k < K)
                v = *reinterpret_cast<const float4*>(&W[(size_t)k * H_DIM + col0 + n]);
            *reinterpret_cast<float4*>(&Bs[kk][n]) = v;
        }
        __syncthreads();

        // ---- inner product over BK ----
#pragma unroll
        for (int kk = 0; kk < BK; kk++) {
            // a pairs: direct 8-byte loads (rows are contiguous in As)
            const unsigned long long* arow =
                reinterpret_cast<const unsigned long long*>(&As[kk][ty * 8]);
            unsigned long long a2[4];
#pragma unroll
            for (int rp = 0; rp < 4; rp++) a2[rp] = arow[rp];

            float4 b0 = *reinterpret_cast<const float4*>(&Bs[kk][tx * 4]);
            float4 b1 = *reinterpret_cast<const float4*>(&Bs[kk][64 + tx * 4]);

            unsigned long long bb[8];
            {
                unsigned r;
                r = __float_as_uint(b0.x); asm("mov.b64 %0, {%1,%1};" : "=l"(bb[0]) : "r"(r));
                r = __float_as_uint(b0.y); asm("mov.b64 %0, {%1,%1};" : "=l"(bb[1]) : "r"(r));
                r = __float_as_uint(b0.z); asm("mov.b64 %0, {%1,%1};" : "=l"(bb[2]) : "r"(r));
                r = __float_as_uint(b0.w); asm("mov.b64 %0, {%1,%1};" : "=l"(bb[3]) : "r"(r));
                r = __float_as_uint(b1.x); asm("mov.b64 %0, {%1,%1};" : "=l"(bb[4]) : "r"(r));
                r = __float_as_uint(b1.y); asm("mov.b64 %0, {%1,%1};" : "=l"(bb[5]) : "r"(r));
                r = __float_as_uint(b1.z); asm("mov.b64 %0, {%1,%1};" : "=l"(bb[6]) : "r"(r));
                r = __float_as_uint(b1.w); asm("mov.b64 %0, {%1,%1};" : "=l"(bb[7]) : "r"(r));
            }
#pragma unroll
            for (int rp = 0; rp < 4; rp++)
#pragma unroll
                for (int c = 0; c < 8; c++)
                    asm("fma.rn.f32x2 %0, %1, %2, %0;"
                        : "+l"(acc[rp][c]) : "l"(a2[rp]), "l"(bb[c]));
        }
        __syncthreads();
    }

    // ---- epilogue: bias + relu ----
    float* dst = (MODE == 0) ? g_h : (MODE == 1) ? g_tmp : out_param;
    float bias0[4], bias1[4];
#pragma unroll
    for (int c = 0; c < 4; c++) {
        bias0[c] = bias[col0 + tx * 4 + c];
        bias1[c] = bias[col0 + 64 + tx * 4 + c];
    }
#pragma unroll
    for (int rp = 0; rp < 4; rp++) {
        int r0 = row0 + ty * 8 + 2 * rp;
        float lo[8], hi[8];
#pragma unroll
        for (int c = 0; c < 8; c++) {
            lo[c] = __uint_as_float((unsigned)(acc[rp][c] & 0xffffffffULL));
            hi[c] = __uint_as_float((unsigned)(acc[rp][c] >> 32));
        }
        float4 w;
        // row r0, first half
        w = make_float4(fmaxf(lo[0] + bias0[0], 0.f), fmaxf(lo[1] + bias0[1], 0.f),
                        fmaxf(lo[2] + bias0[2], 0.f), fmaxf(lo[3] + bias0[3], 0.f));
        *reinterpret_cast<float4*>(&dst[(size_t)r0 * H_DIM + col0 + tx * 4]) = w;
        // row r0, second half
        w = make_float4(fmaxf(lo[4] + bias1[0], 0.f), fmaxf(lo[5] + bias1[1], 0.f),
                        fmaxf(lo[6] + bias1[2], 0.f), fmaxf(lo[7] + bias1[3], 0.f));
        *reinterpret_cast<float4*>(&dst[(size_t)r0 * H_DIM + col0 + 64 + tx * 4]) = w;
        // row r0+1, first half
        w = make_float4(fmaxf(hi[0] + bias0[0], 0.f), fmaxf(hi[1] + bias0[1], 0.f),
                        fmaxf(hi[2] + bias0[2], 0.f), fmaxf(hi[3] + bias0[3], 0.f));
        *reinterpret_cast<float4*>(&dst[(size_t)(r0 + 1) * H_DIM + col0 + tx * 4]) = w;
        // row r0+1, second half
        w = make_float4(fmaxf(hi[4] + bias1[0], 0.f), fmaxf(hi[5] + bias1[1], 0.f),
                        fmaxf(hi[6] + bias1[2], 0.f), fmaxf(hi[7] + bias1[3], 0.f));
        *reinterpret_cast<float4*>(&dst[(size_t)(r0 + 1) * H_DIM + col0 + 64 + tx * 4]) = w;
    }
}

// ---------------- BatchNorm ----------------
__global__ __launch_bounds__(256)
void bn_stats_kernel() {
    int c = threadIdx.x;   // 256 channels
    float s = 0.0f, s2 = 0.0f;
    for (int r = blockIdx.x; r < N_NODES; r += gridDim.x) {
        float v = g_h[(size_t)r * H_DIM + c];
        s += v;
        s2 += v * v;
    }
    atomicAdd(&g_sum[c], s);
    atomicAdd(&g_sumsq[c], s2);
}

__global__ void bn_finalize_kernel(const float* __restrict__ gamma,
                                   const float* __restrict__ beta) {
    int c = threadIdx.x;
    float invN = 1.0f / (float)N_NODES;
    float mu   = g_sum[c] * invN;
    float var  = fmaxf(g_sumsq[c] * invN - mu * mu, 0.0f);
    float rs   = rsqrtf(var + BN_EPS);
    float sc   = rs * gamma[c];
    g_scale[c] = sc;
    g_shift[c] = beta[c] - mu * sc;
}

__global__ __launch_bounds__(256)
void bn_apply_kernel() {
    size_t total4 = (size_t)N_NODES * H_DIM / 4;
    size_t stride = (size_t)gridDim.x * blockDim.x;
    float4* h4 = reinterpret_cast<float4*>(g_h);
    for (size_t i = (size_t)blockIdx.x * blockDim.x + threadIdx.x; i < total4; i += stride) {
        int c0 = (int)((i * 4) & (H_DIM - 1));
        float4 v = h4[i];
        v.x = v.x * g_scale[c0 + 0] + g_shift[c0 + 0];
        v.y = v.y * g_scale[c0 + 1] + g_shift[c0 + 1];
        v.z = v.z * g_scale[c0 + 2] + g_shift[c0 + 2];
        v.w = v.w * g_scale[c0 + 3] + g_shift[c0 + 3];
        h4[i] = v;
    }
}

// ---------------- GINE edge kernel ----------------
// warp per edge (grid-stride). lane owns cols [8*lane, 8*lane+8).
__global__ __launch_bounds__(256)
void edge_kernel(const float* __restrict__ ea,
                 const float* __restrict__ We,
                 const float* __restrict__ be)
{
    const int lane   = threadIdx.x & 31;
    const int warp   = (blockIdx.x * blockDim.x + threadIdx.x) >> 5;
    const int nwarps = (gridDim.x * blockDim.x) >> 5;
    const int cbase  = lane * 8;

    float we[E_DIM][8], bvec[8];
#pragma unroll
    for (int d = 0; d < E_DIM; d++)
#pragma unroll
        for (int j = 0; j < 8; j++)
            we[d][j] = We[d * H_DIM + cbase + j];
#pragma unroll
    for (int j = 0; j < 8; j++) bvec[j] = be[cbase + j];

    for (int e = warp; e < N_EDGES; e += nwarps) {
        int src = g_src[e];
        int dst = g_dst[e];
        float eav = (lane < E_DIM) ? ea[(size_t)e * E_DIM + lane] : 0.0f;

        float acc[8];
#pragma unroll
        for (int j = 0; j < 8; j++) acc[j] = bvec[j];
#pragma unroll
        for (int d = 0; d < E_DIM; d++) {
            float v = __shfl_sync(0xffffffffu, eav, d);
#pragma unroll
            for (int j = 0; j < 8; j++) acc[j] = fmaf(v, we[d][j], acc[j]);
        }

        const float4* hp = reinterpret_cast<const float4*>(&g_h[(size_t)src * H_DIM + cbase]);
        float4 h0 = hp[0];
        float4 h1 = hp[1];

        float m0 = fmaxf(h0.x + acc[0], 0.0f);
        float m1 = fmaxf(h0.y + acc[1], 0.0f);
        float m2 = fmaxf(h0.z + acc[2], 0.0f);
        float m3 = fmaxf(h0.w + acc[3], 0.0f);
        float m4 = fmaxf(h1.x + acc[4], 0.0f);
        float m5 = fmaxf(h1.y + acc[5], 0.0f);
        float m6 = fmaxf(h1.z + acc[6], 0.0f);
        float m7 = fmaxf(h1.w + acc[7], 0.0f);

        float* ap = &g_agg[(size_t)dst * H_DIM + cbase];
        unsigned long long gaddr = (unsigned long long)__cvta_generic_to_global((void*)ap);
        asm volatile("red.global.add.v4.f32 [%0], {%1,%2,%3,%4};"
                     :: "l"(gaddr), "f"(m0), "f"(m1), "f"(m2), "f"(m3) : "memory");
        asm volatile("red.global.add.v4.f32 [%0], {%1,%2,%3,%4};"
                     :: "l"(gaddr + 16), "f"(m4), "f"(m5), "f"(m6), "f"(m7) : "memory");
    }
}

// ---------------- edge_attr passthrough (2nd tuple element) ----------------
__global__ __launch_bounds__(256)
void copy_kernel(const float* __restrict__ src, float* __restrict__ dst, size_t n4) {
    size_t stride = (size_t)gridDim.x * blockDim.x;
    const float4* s4 = reinterpret_cast<const float4*>(src);
    float4* d4 = reinterpret_cast<float4*>(dst);
    for (size_t i = (size_t)blockIdx.x * blockDim.x + threadIdx.x; i < n4; i += stride)
        d4[i] = s4[i];
}

// ---------------- launch ----------------
extern "C" void kernel_launch(void* const* d_in, const int* in_sizes, int n_in,
                              void* d_out, int out_size)
{
    // ---- input order detection by size signature ----
    static const long long SZ_DICT[15] = {
        6889472LL, 1900544LL, 4751360LL, 59392LL, 128LL, 33792LL, 256LL,
        256LL, 256LL, 1280LL, 256LL, 65536LL, 256LL, 65536LL, 256LL };
    static const long long SZ_ALPHA[15] = {
        65536LL, 65536LL, 33792LL, 1280LL, 256LL, 256LL, 256LL, 256LL,
        256LL, 4751360LL, 1900544LL, 256LL, 128LL, 59392LL, 6889472LL };
    static const int ALPHA_TO_DICT[15] = { 11, 13, 5, 9, 12, 14, 6, 10, 8, 2, 1, 7, 4, 3, 0 };

    int perm[15];
    for (int i = 0; i < 15; i++) perm[i] = i;
    if (n_in >= 15) {
        bool dict_ok = true, alpha_ok = true;
        for (int i = 0; i < 15; i++) {
            if ((long long)in_sizes[i] != SZ_DICT[i])  dict_ok  = false;
            if ((long long)in_sizes[i] != SZ_ALPHA[i]) alpha_ok = false;
        }
        if (!dict_ok && alpha_ok)
            for (int i = 0; i < 15; i++) perm[ALPHA_TO_DICT[i]] = i;
    }

    const float* x      = (const float*)d_in[perm[0]];
    const void*  eindex = d_in[perm[1]];
    const float* eattr  = (const float*)d_in[perm[2]];
    const void*  gids   = d_in[perm[3]];
    const float* gemb   = (const float*)d_in[perm[4]];
    const float* W_in   = (const float*)d_in[perm[5]];
    const float* b_in   = (const float*)d_in[perm[6]];
    const float* gamma  = (const float*)d_in[perm[7]];
    const float* beta   = (const float*)d_in[perm[8]];
    const float* We     = (const float*)d_in[perm[9]];
    const float* be     = (const float*)d_in[perm[10]];
    const float* W1     = (const float*)d_in[perm[11]];
    const float* b1     = (const float*)d_in[perm[12]];
    const float* W2     = (const float*)d_in[perm[13]];
    const float* b2     = (const float*)d_in[perm[14]];
    float* out = (float*)d_out;

    dim3 ggrid(N_NODES / 128, H_DIM / 128);   // (464, 2)

    // 0. dtype probe + index normalization (int64 vs int32)
    detect_kernel<<<1, 32>>>((const int*)eindex);
    convert_kernel<<<2048, 256>>>(eindex, gids);

    // 1. zero agg + stats
    zero_kernel<<<2048, 256>>>();

    // 2. h = relu(concat(x, emb) @ W_in + b_in)   -> g_h
    gemm_kernel<0><<<ggrid, 256>>>(x, gemb, W_in, b_in, nullptr, K_IN);

    // 3-5. BatchNorm (training stats, biased var), applied in-place on g_h
    bn_stats_kernel<<<464, 256>>>();
    bn_finalize_kernel<<<1, 256>>>(gamma, beta);
    bn_apply_kernel<<<1024, 256>>>();

    // 6. GINE edge scatter: agg[dst] += relu(h[src] + ea@We + be)
    edge_kernel<<<4096, 256>>>(eattr, We, be);

    // 7. tmp = relu((h + agg) @ W1 + b1)   -> g_tmp
    gemm_kernel<1><<<ggrid, 256>>>(nullptr, nullptr, W1, b1, nullptr, H_DIM);

    // 8. out = relu(tmp @ W2 + b2)         -> d_out
    gemm_kernel<2><<<ggrid, 256>>>(nullptr, nullptr, W2, b2, out, H_DIM);

    // 9. second tuple element: edge_attr passthrough (size derived from out_size)
    long long tail = (long long)out_size - (long long)N_NODES * H_DIM;
    if (tail > 0) {
        size_t n4 = (size_t)tail / 4;
        copy_kernel<<<2048, 256>>>(eattr, out + (size_t)N_NODES * H_DIM, n4);
    }
}